// round 2
// baseline (speedup 1.0000x reference)
#include <cuda_runtime.h>
#include <cstdint>

#define HDIM 256
#define NMAX 50048

// ---------------- static scratch (no allocations allowed) ----------------
__device__ float g_buf0[NMAX * HDIM];   // msg after layer 0
__device__ float g_buf1[NMAX * HDIM];   // msg after layer 1 (gathered by edges)
__device__ float g_accum[NMAX * HDIM];  // scatter-sum
__device__ float g_c2[NMAX * HDIM];     // after combine layer (W2)
__device__ float g_counts[NMAX];        // per-target edge counts
__device__ int   g_idx64;               // 1 if edge_index stored as int64

__device__ __forceinline__ float gelu_exact(float x) {
    // exact erf variant: x * Phi(x)
    return x * normcdff(x);
}

// ---------------- detect int32 vs int64 edge_index ----------------
__global__ void detect_idx_kernel(const void* eidx, int nnodes) {
    const long long* p = (const long long*)eidx;
    int ok64 = 1;
    #pragma unroll 1
    for (int i = 0; i < 64; i++) {
        long long v = p[i];
        if (v < 0 || v >= (long long)nnodes) { ok64 = 0; break; }
    }
    g_idx64 = ok64;
}

// ---------------- GEMM + bias + GELU ----------------
// C[M,256] = gelu( Ain @ W + b ), Ain row-major with 256 cols.
// SPLIT=1: K=512, first 256 k from A (target), next 256 from A2 (accum) scaled
// by 1/max(count,1)  (folds the scatter-mean normalization into the load).
// Tile: BM=128, BN=128, BK=8, 256 threads, 8x8 per-thread.
template<int SPLIT>
__global__ __launch_bounds__(256)
void gemm_bias_gelu(const float* __restrict__ A, const float* __restrict__ A2,
                    const float* __restrict__ counts,
                    const float* __restrict__ W, const float* __restrict__ bias,
                    float* __restrict__ C, int M, int K)
{
    __shared__ __align__(16) float As[8][128];
    __shared__ __align__(16) float Bs[8][128];

    const int tid = threadIdx.x;
    const int rowBlock = blockIdx.y * 128;
    const int colBlock = blockIdx.x * 128;

    const int aRow  = tid >> 1;          // 0..127
    const int aCol4 = (tid & 1) * 4;     // 0 or 4
    const int bRow  = tid >> 5;          // 0..7
    const int bCol4 = (tid & 31) * 4;    // 0..124

    const int tm = (tid >> 4) * 8;       // 0..120
    const int tn = (tid & 15) * 8;       // 0..120

    float acc[8][8];
    #pragma unroll
    for (int i = 0; i < 8; i++)
        #pragma unroll
        for (int j = 0; j < 8; j++) acc[i][j] = 0.0f;

    for (int k0 = 0; k0 < K; k0 += 8) {
        // ---- global loads ----
        float4 av = make_float4(0.f, 0.f, 0.f, 0.f);
        const int gRow = rowBlock + aRow;
        if (gRow < M) {
            const int kk = k0 + aCol4;
            if (SPLIT && kk >= 256) {
                av = *(const float4*)(A2 + (size_t)gRow * 256 + (kk - 256));
                const float inv = 1.0f / fmaxf(counts[gRow], 1.0f);
                av.x *= inv; av.y *= inv; av.z *= inv; av.w *= inv;
            } else {
                av = *(const float4*)(A + (size_t)gRow * 256 + kk);
            }
        }
        const float4 bv = *(const float4*)(W + (size_t)(k0 + bRow) * 256 + colBlock + bCol4);

        __syncthreads();
        As[aCol4 + 0][aRow] = av.x;
        As[aCol4 + 1][aRow] = av.y;
        As[aCol4 + 2][aRow] = av.z;
        As[aCol4 + 3][aRow] = av.w;
        *(float4*)&Bs[bRow][bCol4] = bv;
        __syncthreads();

        #pragma unroll
        for (int k = 0; k < 8; k++) {
            float ar[8], br[8];
            *(float4*)&ar[0] = *(const float4*)&As[k][tm];
            *(float4*)&ar[4] = *(const float4*)&As[k][tm + 4];
            *(float4*)&br[0] = *(const float4*)&Bs[k][tn];
            *(float4*)&br[4] = *(const float4*)&Bs[k][tn + 4];
            #pragma unroll
            for (int i = 0; i < 8; i++)
                #pragma unroll
                for (int j = 0; j < 8; j++)
                    acc[i][j] = fmaf(ar[i], br[j], acc[i][j]);
        }
    }

    // ---- epilogue: bias + gelu ----
    float bb[8];
    #pragma unroll
    for (int j = 0; j < 8; j++) bb[j] = bias[colBlock + tn + j];

    #pragma unroll
    for (int i = 0; i < 8; i++) {
        const int gRow = rowBlock + tm + i;
        if (gRow >= M) break;
        float o[8];
        #pragma unroll
        for (int j = 0; j < 8; j++) o[j] = gelu_exact(acc[i][j] + bb[j]);
        float* dst = C + (size_t)gRow * 256 + colBlock + tn;
        *(float4*)(dst)     = *(float4*)&o[0];
        *(float4*)(dst + 4) = *(float4*)&o[4];
    }
}

// ---------------- edge scatter-sum (vector reductions) ----------------
__global__ void scatter_kernel(const void* __restrict__ eidx,
                               const float* __restrict__ msg,
                               float* __restrict__ accum,
                               float* __restrict__ counts,
                               int E, int Nn)
{
    const int lane = threadIdx.x & 31;
    const int warp = (blockIdx.x * blockDim.x + threadIdx.x) >> 5;
    const int nwarps = (gridDim.x * blockDim.x) >> 5;
    const int flag = g_idx64;
    const long long* p64 = (const long long*)eidx;
    const int*       p32 = (const int*)eidx;

    for (int e = warp; e < E; e += nwarps) {
        int src, dst;
        if (flag) { src = (int)p64[e]; dst = (int)p64[E + e]; }
        else      { src = p32[e];      dst = p32[E + e]; }
        src = min(max(src, 0), Nn - 1);
        dst = min(max(dst, 0), Nn - 1);

        const float4* srow = (const float4*)(msg + (size_t)src * 256);
        const float4 v0 = srow[lane * 2 + 0];
        const float4 v1 = srow[lane * 2 + 1];
        float* d = accum + (size_t)dst * 256 + lane * 8;
        asm volatile("red.global.add.v4.f32 [%0], {%1,%2,%3,%4};"
                     :: "l"(d), "f"(v0.x), "f"(v0.y), "f"(v0.z), "f"(v0.w) : "memory");
        asm volatile("red.global.add.v4.f32 [%0], {%1,%2,%3,%4};"
                     :: "l"(d + 4), "f"(v1.x), "f"(v1.y), "f"(v1.z), "f"(v1.w) : "memory");
        if (lane == 0)
            asm volatile("red.global.add.f32 [%0], %1;"
                         :: "l"(counts + dst), "f"(1.0f) : "memory");
    }
}

// ---------------- final GEMM + bias + GELU + residual + LayerNorm ----------------
// out = LN( gelu(A@W3 + b3) + target ) * gamma + beta
// Tile: BM=64, BN=256 (full row), BK=8, 256 threads. Warp ty owns rows
// ty*8..ty*8+7; lane tx owns cols tx*8..tx*8+7 -> full row lives in one warp.
__global__ __launch_bounds__(256)
void gemm_final_ln(const float* __restrict__ A,
                   const float* __restrict__ W3, const float* __restrict__ b3,
                   const float* __restrict__ target,
                   const float* __restrict__ gamma, const float* __restrict__ beta,
                   float* __restrict__ out, int M)
{
    __shared__ __align__(16) float As[8][64];
    __shared__ __align__(16) float Bs[8][256];

    const int tid = threadIdx.x;
    const int rowBlock = blockIdx.x * 64;
    const int tx = tid & 31, ty = tid >> 5;

    float acc[8][8];
    #pragma unroll
    for (int i = 0; i < 8; i++)
        #pragma unroll
        for (int j = 0; j < 8; j++) acc[i][j] = 0.0f;

    const int b0r = tid >> 6;              // 0..3
    const int bc4 = (tid & 63) * 4;        // 0..252

    for (int k0 = 0; k0 < 256; k0 += 8) {
        float4 av = make_float4(0.f, 0.f, 0.f, 0.f);
        if (tid < 128) {
            const int gRow = rowBlock + (tid >> 1);
            const int kk = k0 + (tid & 1) * 4;
            if (gRow < M) av = *(const float4*)(A + (size_t)gRow * 256 + kk);
        }
        const float4 bv0 = *(const float4*)(W3 + (size_t)(k0 + b0r) * 256 + bc4);
        const float4 bv1 = *(const float4*)(W3 + (size_t)(k0 + b0r + 4) * 256 + bc4);

        __syncthreads();
        if (tid < 128) {
            const int c = (tid & 1) * 4, r = tid >> 1;
            As[c + 0][r] = av.x; As[c + 1][r] = av.y;
            As[c + 2][r] = av.z; As[c + 3][r] = av.w;
        }
        *(float4*)&Bs[b0r][bc4]     = bv0;
        *(float4*)&Bs[b0r + 4][bc4] = bv1;
        __syncthreads();

        #pragma unroll
        for (int k = 0; k < 8; k++) {
            float ar[8], br[8];
            *(float4*)&ar[0] = *(const float4*)&As[k][ty * 8];
            *(float4*)&ar[4] = *(const float4*)&As[k][ty * 8 + 4];
            *(float4*)&br[0] = *(const float4*)&Bs[k][tx * 8];
            *(float4*)&br[4] = *(const float4*)&Bs[k][tx * 8 + 4];
            #pragma unroll
            for (int i = 0; i < 8; i++)
                #pragma unroll
                for (int j = 0; j < 8; j++)
                    acc[i][j] = fmaf(ar[i], br[j], acc[i][j]);
        }
    }

    // epilogue
    const int colBase = tx * 8;
    float bb[8], gg[8], be[8];
    #pragma unroll
    for (int j = 0; j < 8; j++) {
        bb[j] = b3[colBase + j];
        gg[j] = gamma[colBase + j];
        be[j] = beta[colBase + j];
    }

    #pragma unroll
    for (int i = 0; i < 8; i++) {
        const int gRow = rowBlock + ty * 8 + i;
        const bool valid = (gRow < M);
        float vals[8];
        float s = 0.f, sq = 0.f;
        float tg[8];
        if (valid) {
            const float* tr = target + (size_t)gRow * 256 + colBase;
            *(float4*)&tg[0] = *(const float4*)(tr);
            *(float4*)&tg[4] = *(const float4*)(tr + 4);
        } else {
            #pragma unroll
            for (int j = 0; j < 8; j++) tg[j] = 0.f;
        }
        #pragma unroll
        for (int j = 0; j < 8; j++) {
            float v = gelu_exact(acc[i][j] + bb[j]) + tg[j];
            vals[j] = v;
            s += v; sq += v * v;
        }
        #pragma unroll
        for (int off = 16; off > 0; off >>= 1) {
            s  += __shfl_xor_sync(0xFFFFFFFFu, s,  off);
            sq += __shfl_xor_sync(0xFFFFFFFFu, sq, off);
        }
        const float mu  = s * (1.0f / 256.0f);
        const float var = sq * (1.0f / 256.0f) - mu * mu;
        const float inv = rsqrtf(var + 1e-5f);
        if (valid) {
            float o[8];
            #pragma unroll
            for (int j = 0; j < 8; j++)
                o[j] = (vals[j] - mu) * inv * gg[j] + be[j];
            float* dst = out + (size_t)gRow * 256 + colBase;
            *(float4*)(dst)     = *(float4*)&o[0];
            *(float4*)(dst + 4) = *(float4*)&o[4];
        }
    }
}

// ---------------- launch ----------------
extern "C" void kernel_launch(void* const* d_in, const int* in_sizes, int n_in,
                              void* d_out, int out_size)
{
    const float* source = (const float*)d_in[0];
    const float* target = (const float*)d_in[1];
    const void*  eidx   = d_in[2];

    // dim_size may or may not be materialized as an input; detect by size.
    const int base = (n_in > 3 && in_sizes[3] == 1) ? 4 : 3;
    const float* W0 = (const float*)d_in[base + 0];
    const float* b0 = (const float*)d_in[base + 1];
    const float* W1 = (const float*)d_in[base + 2];
    const float* b1 = (const float*)d_in[base + 3];
    const float* W2 = (const float*)d_in[base + 4];
    const float* b2 = (const float*)d_in[base + 5];
    const float* W3 = (const float*)d_in[base + 6];
    const float* b3 = (const float*)d_in[base + 7];
    const float* gm = (const float*)d_in[base + 8];
    const float* bt = (const float*)d_in[base + 9];

    const int M = in_sizes[0] / HDIM;
    const int E = in_sizes[2] / 2;

    float *buf0, *buf1, *accum, *c2, *counts;
    cudaGetSymbolAddress((void**)&buf0,   g_buf0);
    cudaGetSymbolAddress((void**)&buf1,   g_buf1);
    cudaGetSymbolAddress((void**)&accum,  g_accum);
    cudaGetSymbolAddress((void**)&c2,     g_c2);
    cudaGetSymbolAddress((void**)&counts, g_counts);

    cudaMemsetAsync(accum, 0, sizeof(float) * (size_t)M * HDIM);
    cudaMemsetAsync(counts, 0, sizeof(float) * (size_t)M);

    detect_idx_kernel<<<1, 1>>>(eidx, M);

    dim3 gGemm(2, (M + 127) / 128);
    gemm_bias_gelu<0><<<gGemm, 256>>>(source, nullptr, nullptr, W0, b0, buf0, M, 256);
    gemm_bias_gelu<0><<<gGemm, 256>>>(buf0,   nullptr, nullptr, W1, b1, buf1, M, 256);

    scatter_kernel<<<2960, 256>>>(eidx, buf1, accum, counts, E, M);

    gemm_bias_gelu<1><<<gGemm, 256>>>(target, accum, counts, W2, b2, c2, M, 512);

    gemm_final_ln<<<(M + 63) / 64, 256>>>(c2, W3, b3, target, gm, bt, (float*)d_out, M);
}

// round 4
// speedup vs baseline: 1.4569x; 1.4569x over previous
#include <cuda_runtime.h>
#include <cuda_bf16.h>
#include <cstdint>

#define HDIM 256
#define NMAX 50048

// ---------------- static scratch ----------------
__device__ float g_buf0[NMAX * HDIM];
__device__ float g_buf1[NMAX * HDIM];
__device__ float g_accum[NMAX * HDIM];
__device__ float g_c2[NMAX * HDIM];
__device__ float g_counts[NMAX];
__device__ int   g_idx64;

// split weights, transposed to [N, K] (K contiguous)
__device__ __nv_bfloat16 g_w0h[256 * 256], g_w0l[256 * 256];
__device__ __nv_bfloat16 g_w1h[256 * 256], g_w1l[256 * 256];
__device__ __nv_bfloat16 g_w2h[256 * 512], g_w2l[256 * 512];
__device__ __nv_bfloat16 g_w3h[256 * 256], g_w3l[256 * 256];

__device__ __forceinline__ float gelu_exact(float x) { return x * normcdff(x); }

__device__ __forceinline__ uint32_t smem_u32(const void* p) {
    uint32_t a;
    asm("{ .reg .u64 t; cvta.to.shared.u64 t, %1; cvt.u32.u64 %0, t; }" : "=r"(a) : "l"(p));
    return a;
}

#define LDMX4(r0, r1, r2, r3, a) \
    asm volatile("ldmatrix.sync.aligned.m8n8.x4.shared.b16 {%0,%1,%2,%3}, [%4];" \
        : "=r"(r0), "=r"(r1), "=r"(r2), "=r"(r3) : "r"(a))

#define MMA16816(c, a0, a1, a2, a3, b0, b1) \
    asm volatile("mma.sync.aligned.m16n8k16.row.col.f32.bf16.bf16.f32 " \
        "{%0,%1,%2,%3}, {%4,%5,%6,%7}, {%8,%9}, {%0,%1,%2,%3};" \
        : "+f"((c)[0]), "+f"((c)[1]), "+f"((c)[2]), "+f"((c)[3]) \
        : "r"(a0), "r"(a1), "r"(a2), "r"(a3), "r"(b0), "r"(b1))

#define CPASYNC16(sm, gp) \
    asm volatile("cp.async.ca.shared.global [%0], [%1], 16;" :: "r"(sm), "l"(gp))
#define CPASYNC_COMMIT() asm volatile("cp.async.commit_group;" ::: "memory")
#define CPASYNC_WAIT0()  asm volatile("cp.async.wait_group 0;" ::: "memory")

__device__ __forceinline__ uint32_t pack_bf2(__nv_bfloat16 a, __nv_bfloat16 b) {
    __nv_bfloat162 t = __halves2bfloat162(a, b);
    return *(uint32_t*)&t;
}

// ---------------- small kernels ----------------
__global__ void detect_idx_kernel(const void* eidx, int nnodes) {
    const long long* p = (const long long*)eidx;
    int ok64 = 1;
    #pragma unroll 1
    for (int i = 0; i < 64; i++) {
        long long v = p[i];
        if (v < 0 || v >= (long long)nnodes) { ok64 = 0; break; }
    }
    g_idx64 = ok64;
}

// W[K,N] fp32 -> Wt_hi/Wt_lo[N,K] bf16 split
__global__ void wprep_kernel(const float* __restrict__ W,
                             __nv_bfloat16* __restrict__ Wh,
                             __nv_bfloat16* __restrict__ Wl, int K, int N) {
    int idx = blockIdx.x * blockDim.x + threadIdx.x;
    if (idx >= N * K) return;
    int n = idx / K, k = idx - n * K;
    float w = W[(size_t)k * N + n];
    __nv_bfloat16 h = __float2bfloat16_rn(w);
    Wh[idx] = h;
    Wl[idx] = __float2bfloat16_rn(w - __bfloat162float(h));
}

// ---------------- mma.sync GEMM (+bias+GELU [+residual]) ----------------
// C[M,256] = act(A @ Wt^T + b). Wt [N,Kw] bf16 hi/lo. 3xBF16 split accumulation.
// CTA tile 128x128, BK=32, 256 thr = 8 warps (2m x 4n), warp tile 64x32.
// SMEM (bytes): AH[0,10240) AL[10240,20480) B stages at 20480 (each BH+BL=20480).
#define SA_H 0
#define SA_L 10240
#define SB_BASE 20480
#define SB_STAGE 20480
#define SM_TOTAL (20480 + 2 * 20480)

template<int KCHUNKS, int SPLIT, int RESID>
__global__ __launch_bounds__(256, 1)
void gemm_mma(const float* __restrict__ A, const float* __restrict__ A2,
              const float* __restrict__ counts,
              const __nv_bfloat16* __restrict__ Wh, const __nv_bfloat16* __restrict__ Wl,
              int Kw, const float* __restrict__ bias, const float* __restrict__ resid,
              float* __restrict__ C, int M)
{
    extern __shared__ char smem[];
    const uint32_t sb = smem_u32(smem);
    const int tid = threadIdx.x;
    const int wid = tid >> 5, lane = tid & 31;
    const int rowBlock = blockIdx.y * 128;
    const int colBlock = blockIdx.x * 128;

    const int warp_m = wid & 1;          // 0..1 -> m offset *64
    const int warp_n = wid >> 1;         // 0..3 -> n offset *32

    float acc[4][4][4];
    #pragma unroll
    for (int a = 0; a < 4; a++)
        #pragma unroll
        for (int b = 0; b < 4; b++)
            #pragma unroll
            for (int c = 0; c < 4; c++) acc[a][b][c] = 0.0f;

    // A staging assignment: thread -> row tid/2, 16 cols at (tid&1)*16
    const int arow = tid >> 1;
    const int acb  = (tid & 1) * 16;

    // ldmatrix per-lane addressing
    const int a_rowin = (lane & 7) | (((lane >> 3) & 1) << 3);  // row within 16
    const int a_koff  = ((lane >> 4) & 1) * 8;
    const uint32_t a_byte = (uint32_t)((warp_m * 64 + a_rowin) * 80 + a_koff * 2);
    const int b_rowin = ((lane >> 4) & 1) * 8 + (lane & 7);     // n within 16
    const int b_koff  = ((lane >> 3) & 1) * 8;
    const uint32_t b_byte = (uint32_t)((warp_n * 32 + b_rowin) * 80 + b_koff * 2);

    float ar[16];
    // ---- A register prefetch for chunk ch ----
    auto loadA = [&](int ch) {
        const int gr = rowBlock + arow;
        #pragma unroll
        for (int j = 0; j < 16; j++) ar[j] = 0.0f;
        if (gr < M) {
            const int gk = ch * 32 + acb;
            const float* src;
            float sc = 1.0f;
            if (SPLIT && gk >= 256) {
                src = A2 + (size_t)gr * 256 + (gk - 256);
                sc = 1.0f / fmaxf(counts[gr], 1.0f);
            } else {
                src = A + (size_t)gr * 256 + gk;
            }
            #pragma unroll
            for (int q = 0; q < 4; q++) {
                float4 v = *(const float4*)(src + q * 4);
                ar[q * 4 + 0] = v.x * sc; ar[q * 4 + 1] = v.y * sc;
                ar[q * 4 + 2] = v.z * sc; ar[q * 4 + 3] = v.w * sc;
            }
        }
    };
    auto storeA = [&]() {
        uint32_t hp[8], lp[8];
        #pragma unroll
        for (int j = 0; j < 8; j++) {
            __nv_bfloat16 h0 = __float2bfloat16_rn(ar[2 * j]);
            __nv_bfloat16 h1 = __float2bfloat16_rn(ar[2 * j + 1]);
            __nv_bfloat16 l0 = __float2bfloat16_rn(ar[2 * j]     - __bfloat162float(h0));
            __nv_bfloat16 l1 = __float2bfloat16_rn(ar[2 * j + 1] - __bfloat162float(h1));
            hp[j] = pack_bf2(h0, h1);
            lp[j] = pack_bf2(l0, l1);
        }
        const uint32_t off = (uint32_t)(arow * 80 + acb * 2);
        *(uint4*)(smem + SA_H + off)      = *(uint4*)&hp[0];
        *(uint4*)(smem + SA_H + off + 16) = *(uint4*)&hp[4];
        *(uint4*)(smem + SA_L + off)      = *(uint4*)&lp[0];
        *(uint4*)(smem + SA_L + off + 16) = *(uint4*)&lp[4];
    };
    auto issueB = [&](int ch, int st) {
        const int kbase = ch * 32;
        const uint32_t bh = sb + SB_BASE + st * SB_STAGE;
        const uint32_t bl = bh + 10240;
        #pragma unroll
        for (int q = 0; q < 2; q++) {
            const int s = tid * 2 + q;       // 0..511
            const int n = s >> 2, p = s & 3;
            const size_t gofs = (size_t)(colBlock + n) * Kw + kbase + p * 8;
            const uint32_t so = (uint32_t)(n * 80 + p * 16);
            CPASYNC16(bh + so, Wh + gofs);
            CPASYNC16(bl + so, Wl + gofs);
        }
        CPASYNC_COMMIT();
    };

    // ---- pipeline ----
    issueB(0, 0);
    loadA(0);
    int st = 0;
    for (int ch = 0; ch < KCHUNKS; ch++) {
        storeA();
        CPASYNC_WAIT0();
        __syncthreads();
        if (ch + 1 < KCHUNKS) {
            issueB(ch + 1, st ^ 1);
            loadA(ch + 1);
        }
        // ---- compute chunk from SMEM stage st ----
        const uint32_t aH = sb + SA_H + a_byte;
        const uint32_t aL = sb + SA_L + a_byte;
        const uint32_t bH = sb + SB_BASE + st * SB_STAGE + b_byte;
        const uint32_t bL = bH + 10240;
        #pragma unroll
        for (int s = 0; s < 2; s++) {
            uint32_t ah[4][4], al[4][4], bh[2][4], bl[2][4];
            #pragma unroll
            for (int mt = 0; mt < 4; mt++) {
                LDMX4(ah[mt][0], ah[mt][1], ah[mt][2], ah[mt][3], aH + mt * 16 * 80 + s * 32);
                LDMX4(al[mt][0], al[mt][1], al[mt][2], al[mt][3], aL + mt * 16 * 80 + s * 32);
            }
            #pragma unroll
            for (int np = 0; np < 2; np++) {
                LDMX4(bh[np][0], bh[np][1], bh[np][2], bh[np][3], bH + np * 16 * 80 + s * 32);
                LDMX4(bl[np][0], bl[np][1], bl[np][2], bl[np][3], bL + np * 16 * 80 + s * 32);
            }
            #pragma unroll
            for (int mt = 0; mt < 4; mt++)
                #pragma unroll
                for (int nt = 0; nt < 4; nt++) {
                    const int np = nt >> 1, ix = (nt & 1) * 2;
                    MMA16816(acc[mt][nt], ah[mt][0], ah[mt][1], ah[mt][2], ah[mt][3],
                             bh[np][ix], bh[np][ix + 1]);
                    MMA16816(acc[mt][nt], ah[mt][0], ah[mt][1], ah[mt][2], ah[mt][3],
                             bl[np][ix], bl[np][ix + 1]);
                    MMA16816(acc[mt][nt], al[mt][0], al[mt][1], al[mt][2], al[mt][3],
                             bh[np][ix], bh[np][ix + 1]);
                }
        }
        __syncthreads();
        st ^= 1;
    }

    // ---- epilogue ----
    const int qr = lane >> 2;
    const int qc = (lane & 3) * 2;
    float bv[4][2];
    #pragma unroll
    for (int nt = 0; nt < 4; nt++) {
        const int col = colBlock + warp_n * 32 + nt * 8 + qc;
        bv[nt][0] = bias[col];
        bv[nt][1] = bias[col + 1];
    }
    #pragma unroll
    for (int mt = 0; mt < 4; mt++)
        #pragma unroll
        for (int half = 0; half < 2; half++) {
            const int row = rowBlock + warp_m * 64 + mt * 16 + qr + half * 8;
            if (row >= M) continue;
            #pragma unroll
            for (int nt = 0; nt < 4; nt++) {
                const int col = colBlock + warp_n * 32 + nt * 8 + qc;
                float v0 = gelu_exact(acc[mt][nt][half * 2 + 0] + bv[nt][0]);
                float v1 = gelu_exact(acc[mt][nt][half * 2 + 1] + bv[nt][1]);
                if (RESID) {
                    const float2 rv = *(const float2*)(resid + (size_t)row * 256 + col);
                    v0 += rv.x; v1 += rv.y;
                }
                float2 o = make_float2(v0, v1);
                *(float2*)(C + (size_t)row * 256 + col) = o;
            }
        }
}

// ---------------- edge scatter-sum ----------------
__global__ void scatter_kernel(const void* __restrict__ eidx,
                               const float* __restrict__ msg,
                               float* __restrict__ accum,
                               float* __restrict__ counts,
                               int E, int Nn)
{
    const int lane = threadIdx.x & 31;
    const int warp = (blockIdx.x * blockDim.x + threadIdx.x) >> 5;
    const int nwarps = (gridDim.x * blockDim.x) >> 5;
    const int flag = g_idx64;
    const long long* p64 = (const long long*)eidx;
    const int*       p32 = (const int*)eidx;

    for (int e = warp; e < E; e += nwarps) {
        int src, dst;
        if (flag) { src = (int)p64[e]; dst = (int)p64[E + e]; }
        else      { src = p32[e];      dst = p32[E + e]; }
        src = min(max(src, 0), Nn - 1);
        dst = min(max(dst, 0), Nn - 1);

        const float4* srow = (const float4*)(msg + (size_t)src * 256);
        const float4 v0 = srow[lane * 2 + 0];
        const float4 v1 = srow[lane * 2 + 1];
        float* d = accum + (size_t)dst * 256 + lane * 8;
        asm volatile("red.global.add.v4.f32 [%0], {%1,%2,%3,%4};"
                     :: "l"(d), "f"(v0.x), "f"(v0.y), "f"(v0.z), "f"(v0.w) : "memory");
        asm volatile("red.global.add.v4.f32 [%0], {%1,%2,%3,%4};"
                     :: "l"(d + 4), "f"(v1.x), "f"(v1.y), "f"(v1.z), "f"(v1.w) : "memory");
        if (lane == 0)
            asm volatile("red.global.add.f32 [%0], %1;"
                         :: "l"(counts + dst), "f"(1.0f) : "memory");
    }
}

// ---------------- LayerNorm (warp per row) ----------------
__global__ __launch_bounds__(256)
void ln_kernel(const float* __restrict__ X, const float* __restrict__ gamma,
               const float* __restrict__ beta, float* __restrict__ out, int M)
{
    const int warp = (blockIdx.x * blockDim.x + threadIdx.x) >> 5;
    const int lane = threadIdx.x & 31;
    if (warp >= M) return;
    const float* xp = X + (size_t)warp * 256 + lane * 8;
    float v[8];
    *(float4*)&v[0] = *(const float4*)(xp);
    *(float4*)&v[4] = *(const float4*)(xp + 4);
    float s = 0.f, sq = 0.f;
    #pragma unroll
    for (int j = 0; j < 8; j++) { s += v[j]; sq += v[j] * v[j]; }
    #pragma unroll
    for (int off = 16; off > 0; off >>= 1) {
        s  += __shfl_xor_sync(0xFFFFFFFFu, s,  off);
        sq += __shfl_xor_sync(0xFFFFFFFFu, sq, off);
    }
    const float mu  = s * (1.0f / 256.0f);
    const float var = sq * (1.0f / 256.0f) - mu * mu;
    const float inv = rsqrtf(var + 1e-5f);
    float o[8];
    #pragma unroll
    for (int j = 0; j < 8; j++)
        o[j] = (v[j] - mu) * inv * gamma[lane * 8 + j] + beta[lane * 8 + j];
    float* dp = out + (size_t)warp * 256 + lane * 8;
    *(float4*)(dp)     = *(float4*)&o[0];
    *(float4*)(dp + 4) = *(float4*)&o[4];
}

// ---------------- launch ----------------
extern "C" void kernel_launch(void* const* d_in, const int* in_sizes, int n_in,
                              void* d_out, int out_size)
{
    const float* source = (const float*)d_in[0];
    const float* target = (const float*)d_in[1];
    const void*  eidx   = d_in[2];
    const int base = (n_in > 3 && in_sizes[3] == 1) ? 4 : 3;
    const float* W0 = (const float*)d_in[base + 0];
    const float* b0 = (const float*)d_in[base + 1];
    const float* W1 = (const float*)d_in[base + 2];
    const float* b1 = (const float*)d_in[base + 3];
    const float* W2 = (const float*)d_in[base + 4];
    const float* b2 = (const float*)d_in[base + 5];
    const float* W3 = (const float*)d_in[base + 6];
    const float* b3 = (const float*)d_in[base + 7];
    const float* gm = (const float*)d_in[base + 8];
    const float* bt = (const float*)d_in[base + 9];

    const int M = in_sizes[0] / HDIM;
    const int E = in_sizes[2] / 2;

    float *buf0, *buf1, *accum, *c2, *counts;
    cudaGetSymbolAddress((void**)&buf0,   g_buf0);
    cudaGetSymbolAddress((void**)&buf1,   g_buf1);
    cudaGetSymbolAddress((void**)&accum,  g_accum);
    cudaGetSymbolAddress((void**)&c2,     g_c2);
    cudaGetSymbolAddress((void**)&counts, g_counts);
    __nv_bfloat16 *w0h, *w0l, *w1h, *w1l, *w2h, *w2l, *w3h, *w3l;
    cudaGetSymbolAddress((void**)&w0h, g_w0h); cudaGetSymbolAddress((void**)&w0l, g_w0l);
    cudaGetSymbolAddress((void**)&w1h, g_w1h); cudaGetSymbolAddress((void**)&w1l, g_w1l);
    cudaGetSymbolAddress((void**)&w2h, g_w2h); cudaGetSymbolAddress((void**)&w2l, g_w2l);
    cudaGetSymbolAddress((void**)&w3h, g_w3h); cudaGetSymbolAddress((void**)&w3l, g_w3l);

    cudaFuncSetAttribute(gemm_mma<8, 0, 0>,  cudaFuncAttributeMaxDynamicSharedMemorySize, SM_TOTAL);
    cudaFuncSetAttribute(gemm_mma<16, 1, 0>, cudaFuncAttributeMaxDynamicSharedMemorySize, SM_TOTAL);
    cudaFuncSetAttribute(gemm_mma<8, 0, 1>,  cudaFuncAttributeMaxDynamicSharedMemorySize, SM_TOTAL);

    cudaMemsetAsync(accum, 0, sizeof(float) * (size_t)M * HDIM);
    cudaMemsetAsync(counts, 0, sizeof(float) * (size_t)M);

    detect_idx_kernel<<<1, 1>>>(eidx, M);
    wprep_kernel<<<(256 * 256 + 255) / 256, 256>>>(W0, w0h, w0l, 256, 256);
    wprep_kernel<<<(256 * 256 + 255) / 256, 256>>>(W1, w1h, w1l, 256, 256);
    wprep_kernel<<<(512 * 256 + 255) / 256, 256>>>(W2, w2h, w2l, 512, 256);
    wprep_kernel<<<(256 * 256 + 255) / 256, 256>>>(W3, w3h, w3l, 256, 256);

    const dim3 gG(2, (M + 127) / 128);
    gemm_mma<8, 0, 0><<<gG, 256, SM_TOTAL>>>(source, nullptr, nullptr, w0h, w0l, 256, b0, nullptr, buf0, M);
    gemm_mma<8, 0, 0><<<gG, 256, SM_TOTAL>>>(buf0,   nullptr, nullptr, w1h, w1l, 256, b1, nullptr, buf1, M);

    scatter_kernel<<<2960, 256>>>(eidx, buf1, accum, counts, E, M);

    gemm_mma<16, 1, 0><<<gG, 256, SM_TOTAL>>>(target, accum, counts, w2h, w2l, 512, b2, nullptr, c2, M);
    gemm_mma<8, 0, 1><<<gG, 256, SM_TOTAL>>>(c2, nullptr, nullptr, w3h, w3l, 256, b3, target, buf0, M);

    ln_kernel<<<(M * 32 + 255) / 256, 256>>>(buf0, gm, bt, (float*)d_out, M);
}

// round 6
// speedup vs baseline: 1.6292x; 1.1182x over previous
#include <cuda_runtime.h>
#include <cuda_bf16.h>
#include <cstdint>

#define HDIM 256
#define NMAX 50048

// ---------------- static scratch ----------------
__device__ float g_buf0[NMAX * HDIM];
__device__ float g_buf1[NMAX * HDIM];
__device__ float g_accum[NMAX * HDIM];
__device__ float g_c2[NMAX * HDIM];
__device__ float g_counts[NMAX];
__device__ int   g_idx64;

// split weights, transposed to [N, K] (K contiguous)
__device__ __nv_bfloat16 g_w0h[256 * 256], g_w0l[256 * 256];
__device__ __nv_bfloat16 g_w1h[256 * 256], g_w1l[256 * 256];
__device__ __nv_bfloat16 g_w2h[256 * 512], g_w2l[256 * 512];
__device__ __nv_bfloat16 g_w3h[256 * 256], g_w3l[256 * 256];

__device__ __forceinline__ float gelu_exact(float x) { return x * normcdff(x); }

__device__ __forceinline__ uint32_t smem_u32(const void* p) {
    uint32_t a;
    asm("{ .reg .u64 t; cvta.to.shared.u64 t, %1; cvt.u32.u64 %0, t; }" : "=r"(a) : "l"(p));
    return a;
}

#define LDMX4(r0, r1, r2, r3, a) \
    asm volatile("ldmatrix.sync.aligned.m8n8.x4.shared.b16 {%0,%1,%2,%3}, [%4];" \
        : "=r"(r0), "=r"(r1), "=r"(r2), "=r"(r3) : "r"(a))

#define MMA16816(c, a0, a1, a2, a3, b0, b1) \
    asm volatile("mma.sync.aligned.m16n8k16.row.col.f32.bf16.bf16.f32 " \
        "{%0,%1,%2,%3}, {%4,%5,%6,%7}, {%8,%9}, {%0,%1,%2,%3};" \
        : "+f"((c)[0]), "+f"((c)[1]), "+f"((c)[2]), "+f"((c)[3]) \
        : "r"(a0), "r"(a1), "r"(a2), "r"(a3), "r"(b0), "r"(b1))

#define CPASYNC16(sm, gp) \
    asm volatile("cp.async.ca.shared.global [%0], [%1], 16;" :: "r"(sm), "l"(gp))
#define CPASYNC_COMMIT() asm volatile("cp.async.commit_group;" ::: "memory")
#define CPASYNC_WAIT2()  asm volatile("cp.async.wait_group 2;" ::: "memory")

__device__ __forceinline__ uint32_t pack_bf2(__nv_bfloat16 a, __nv_bfloat16 b) {
    __nv_bfloat162 t = __halves2bfloat162(a, b);
    return *(uint32_t*)&t;
}

// ---------------- small kernels ----------------
__global__ void detect_idx_kernel(const void* eidx, int nnodes) {
    const long long* p = (const long long*)eidx;
    int ok64 = 1;
    #pragma unroll 1
    for (int i = 0; i < 64; i++) {
        long long v = p[i];
        if (v < 0 || v >= (long long)nnodes) { ok64 = 0; break; }
    }
    g_idx64 = ok64;
}

// W[K,N] fp32 -> Wt_hi/Wt_lo[N,K] bf16 split
__global__ void wprep_kernel(const float* __restrict__ W,
                             __nv_bfloat16* __restrict__ Wh,
                             __nv_bfloat16* __restrict__ Wl, int K, int N) {
    int idx = blockIdx.x * blockDim.x + threadIdx.x;
    if (idx >= N * K) return;
    int n = idx / K, k = idx - n * K;
    float w = W[(size_t)k * N + n];
    __nv_bfloat16 h = __float2bfloat16_rn(w);
    Wh[idx] = h;
    Wl[idx] = __float2bfloat16_rn(w - __bfloat162float(h));
}

// ---------------- mma.sync GEMM (+bias+GELU [+residual]) ----------------
// C[M,256] = act(A @ Wt^T + b). 3xBF16 split. CTA 128x128, BK=32, 512 thr =
// 16 warps (4m x 4n), warp tile 32x32. A double-buffered (reg-staged convert),
// B 4-stage cp.async ring (4 stages so the in-flight write target is always
// >=2 stages away from any stage a lagging warp may still be reading with only
// ONE __syncthreads per chunk). wait_group 2 at top of each chunk.
// SMEM: A stages [0,20480),[20480,40960) (hi +0, lo +10240)
//       B stages 40960 + st*20480 (hi +0, lo +10240), st = ch & 3. Total 122880.
#define SA_BASE 0
#define SA_STAGE 20480
#define SB_BASE 40960
#define SB_STAGE 20480
#define HL_OFF 10240
#define SM_TOTAL 122880

template<int KCHUNKS, int SPLIT, int RESID>
__global__ __launch_bounds__(512, 1)
void gemm_mma(const float* __restrict__ A, const float* __restrict__ A2,
              const float* __restrict__ counts,
              const __nv_bfloat16* __restrict__ Wh, const __nv_bfloat16* __restrict__ Wl,
              int Kw, const float* __restrict__ bias, const float* __restrict__ resid,
              float* __restrict__ C, int M)
{
    extern __shared__ char smem[];
    const uint32_t sb = smem_u32(smem);
    const int tid = threadIdx.x;
    const int wid = tid >> 5, lane = tid & 31;
    const int rowBlock = blockIdx.y * 128;
    const int colBlock = blockIdx.x * 128;

    const int warp_m = wid & 3;          // 0..3 -> m offset *32
    const int warp_n = wid >> 2;         // 0..3 -> n offset *32

    float acc[2][4][4];
    #pragma unroll
    for (int a = 0; a < 2; a++)
        #pragma unroll
        for (int b = 0; b < 4; b++)
            #pragma unroll
            for (int c = 0; c < 4; c++) acc[a][b][c] = 0.0f;

    // A staging: thread -> row tid/4, 8 cols at (tid&3)*8
    const int arow = tid >> 2;
    const int acb  = (tid & 3) * 8;

    // ldmatrix per-lane addressing (stride 80 bytes per row)
    const int a_rowin = (lane & 7) | (((lane >> 3) & 1) << 3);
    const int a_koff  = ((lane >> 4) & 1) * 8;
    const uint32_t a_byte = (uint32_t)((warp_m * 32 + a_rowin) * 80 + a_koff * 2);
    const int b_rowin = ((lane >> 4) & 1) * 8 + (lane & 7);
    const int b_koff  = ((lane >> 3) & 1) * 8;
    const uint32_t b_byte = (uint32_t)((warp_n * 32 + b_rowin) * 80 + b_koff * 2);

    float ar[8];
    auto loadA = [&](int ch) {
        const int gr = rowBlock + arow;
        #pragma unroll
        for (int j = 0; j < 8; j++) ar[j] = 0.0f;
        if (gr < M) {
            const int gk = ch * 32 + acb;
            const float* src;
            float sc = 1.0f;
            if (SPLIT && gk >= 256) {
                src = A2 + (size_t)gr * 256 + (gk - 256);
                sc = 1.0f / fmaxf(counts[gr], 1.0f);
            } else {
                src = A + (size_t)gr * 256 + gk;
            }
            float4 v0 = *(const float4*)src;
            float4 v1 = *(const float4*)(src + 4);
            ar[0] = v0.x * sc; ar[1] = v0.y * sc; ar[2] = v0.z * sc; ar[3] = v0.w * sc;
            ar[4] = v1.x * sc; ar[5] = v1.y * sc; ar[6] = v1.z * sc; ar[7] = v1.w * sc;
        }
    };
    auto storeA = [&](int stA) {
        uint32_t hp[4], lp[4];
        #pragma unroll
        for (int j = 0; j < 4; j++) {
            __nv_bfloat16 h0 = __float2bfloat16_rn(ar[2 * j]);
            __nv_bfloat16 h1 = __float2bfloat16_rn(ar[2 * j + 1]);
            __nv_bfloat16 l0 = __float2bfloat16_rn(ar[2 * j]     - __bfloat162float(h0));
            __nv_bfloat16 l1 = __float2bfloat16_rn(ar[2 * j + 1] - __bfloat162float(h1));
            hp[j] = pack_bf2(h0, h1);
            lp[j] = pack_bf2(l0, l1);
        }
        const uint32_t off = (uint32_t)(SA_BASE + stA * SA_STAGE + arow * 80 + acb * 2);
        *(uint4*)(smem + off)          = *(uint4*)&hp[0];
        *(uint4*)(smem + off + HL_OFF) = *(uint4*)&lp[0];
    };
    auto issueB = [&](int ch) {
        if (ch < KCHUNKS) {
            const int st = ch & 3;
            const uint32_t bh = sb + SB_BASE + st * SB_STAGE;
            const int n = tid >> 2, p = tid & 3;
            const size_t gofs = (size_t)(colBlock + n) * Kw + ch * 32 + p * 8;
            const uint32_t so = (uint32_t)(n * 80 + p * 16);
            CPASYNC16(bh + so, Wh + gofs);
            CPASYNC16(bh + HL_OFF + so, Wl + gofs);
        }
        CPASYNC_COMMIT();
    };

    // ---- prologue ----
    issueB(0);
    issueB(1);
    loadA(0);
    storeA(0);

    // ---- main loop: one sync per chunk ----
    for (int ch = 0; ch < KCHUNKS; ch++) {
        issueB(ch + 2);
        const bool more = (ch + 1 < KCHUNKS);
        if (more) loadA(ch + 1);
        CPASYNC_WAIT2();
        __syncthreads();

        const uint32_t aBase = sb + SA_BASE + (ch & 1) * SA_STAGE + a_byte;
        const uint32_t bBase = sb + SB_BASE + (ch & 3) * SB_STAGE + b_byte;
        #pragma unroll
        for (int s = 0; s < 2; s++) {
            uint32_t ah[2][4], al[2][4], bh[2][4], bl[2][4];
            #pragma unroll
            for (int mt = 0; mt < 2; mt++) {
                LDMX4(ah[mt][0], ah[mt][1], ah[mt][2], ah[mt][3], aBase + mt * 16 * 80 + s * 32);
                LDMX4(al[mt][0], al[mt][1], al[mt][2], al[mt][3], aBase + HL_OFF + mt * 16 * 80 + s * 32);
            }
            #pragma unroll
            for (int np = 0; np < 2; np++) {
                LDMX4(bh[np][0], bh[np][1], bh[np][2], bh[np][3], bBase + np * 16 * 80 + s * 32);
                LDMX4(bl[np][0], bl[np][1], bl[np][2], bl[np][3], bBase + HL_OFF + np * 16 * 80 + s * 32);
            }
            #pragma unroll
            for (int mt = 0; mt < 2; mt++)
                #pragma unroll
                for (int nt = 0; nt < 4; nt++) {
                    const int np = nt >> 1, ix = (nt & 1) * 2;
                    MMA16816(acc[mt][nt], ah[mt][0], ah[mt][1], ah[mt][2], ah[mt][3],
                             bh[np][ix], bh[np][ix + 1]);
                    MMA16816(acc[mt][nt], ah[mt][0], ah[mt][1], ah[mt][2], ah[mt][3],
                             bl[np][ix], bl[np][ix + 1]);
                    MMA16816(acc[mt][nt], al[mt][0], al[mt][1], al[mt][2], al[mt][3],
                             bh[np][ix], bh[np][ix + 1]);
                }
        }
        if (more) storeA((ch + 1) & 1);
    }

    // ---- epilogue ----
    const int qr = lane >> 2;
    const int qc = (lane & 3) * 2;
    float bv[4][2];
    #pragma unroll
    for (int nt = 0; nt < 4; nt++) {
        const int col = colBlock + warp_n * 32 + nt * 8 + qc;
        bv[nt][0] = bias[col];
        bv[nt][1] = bias[col + 1];
    }
    #pragma unroll
    for (int mt = 0; mt < 2; mt++)
        #pragma unroll
        for (int half = 0; half < 2; half++) {
            const int row = rowBlock + warp_m * 32 + mt * 16 + qr + half * 8;
            if (row >= M) continue;
            #pragma unroll
            for (int nt = 0; nt < 4; nt++) {
                const int col = colBlock + warp_n * 32 + nt * 8 + qc;
                float v0 = gelu_exact(acc[mt][nt][half * 2 + 0] + bv[nt][0]);
                float v1 = gelu_exact(acc[mt][nt][half * 2 + 1] + bv[nt][1]);
                if (RESID) {
                    const float2 rv = *(const float2*)(resid + (size_t)row * 256 + col);
                    v0 += rv.x; v1 += rv.y;
                }
                float2 o = make_float2(v0, v1);
                *(float2*)(C + (size_t)row * 256 + col) = o;
            }
        }
}

// ---------------- edge scatter-sum ----------------
__global__ void scatter_kernel(const void* __restrict__ eidx,
                               const float* __restrict__ msg,
                               float* __restrict__ accum,
                               float* __restrict__ counts,
                               int E, int Nn)
{
    const int lane = threadIdx.x & 31;
    const int warp = (blockIdx.x * blockDim.x + threadIdx.x) >> 5;
    const int nwarps = (gridDim.x * blockDim.x) >> 5;
    const int flag = g_idx64;
    const long long* p64 = (const long long*)eidx;
    const int*       p32 = (const int*)eidx;

    for (int e = warp; e < E; e += nwarps) {
        int src, dst;
        if (flag) { src = (int)p64[e]; dst = (int)p64[E + e]; }
        else      { src = p32[e];      dst = p32[E + e]; }
        src = min(max(src, 0), Nn - 1);
        dst = min(max(dst, 0), Nn - 1);

        const float4* srow = (const float4*)(msg + (size_t)src * 256);
        const float4 v0 = srow[lane * 2 + 0];
        const float4 v1 = srow[lane * 2 + 1];
        float* d = accum + (size_t)dst * 256 + lane * 8;
        asm volatile("red.global.add.v4.f32 [%0], {%1,%2,%3,%4};"
                     :: "l"(d), "f"(v0.x), "f"(v0.y), "f"(v0.z), "f"(v0.w) : "memory");
        asm volatile("red.global.add.v4.f32 [%0], {%1,%2,%3,%4};"
                     :: "l"(d + 4), "f"(v1.x), "f"(v1.y), "f"(v1.z), "f"(v1.w) : "memory");
        if (lane == 0)
            asm volatile("red.global.add.f32 [%0], %1;"
                         :: "l"(counts + dst), "f"(1.0f) : "memory");
    }
}

// ---------------- LayerNorm (warp per row) ----------------
__global__ __launch_bounds__(256)
void ln_kernel(const float* __restrict__ X, const float* __restrict__ gamma,
               const float* __restrict__ beta, float* __restrict__ out, int M)
{
    const int warp = (blockIdx.x * blockDim.x + threadIdx.x) >> 5;
    const int lane = threadIdx.x & 31;
    if (warp >= M) return;
    const float* xp = X + (size_t)warp * 256 + lane * 8;
    float v[8];
    *(float4*)&v[0] = *(const float4*)(xp);
    *(float4*)&v[4] = *(const float4*)(xp + 4);
    float s = 0.f, sq = 0.f;
    #pragma unroll
    for (int j = 0; j < 8; j++) { s += v[j]; sq += v[j] * v[j]; }
    #pragma unroll
    for (int off = 16; off > 0; off >>= 1) {
        s  += __shfl_xor_sync(0xFFFFFFFFu, s,  off);
        sq += __shfl_xor_sync(0xFFFFFFFFu, sq, off);
    }
    const float mu  = s * (1.0f / 256.0f);
    const float var = sq * (1.0f / 256.0f) - mu * mu;
    const float inv = rsqrtf(var + 1e-5f);
    float o[8];
    #pragma unroll
    for (int j = 0; j < 8; j++)
        o[j] = (v[j] - mu) * inv * gamma[lane * 8 + j] + beta[lane * 8 + j];
    float* dp = out + (size_t)warp * 256 + lane * 8;
    *(float4*)(dp)     = *(float4*)&o[0];
    *(float4*)(dp + 4) = *(float4*)&o[4];
}

// ---------------- launch ----------------
extern "C" void kernel_launch(void* const* d_in, const int* in_sizes, int n_in,
                              void* d_out, int out_size)
{
    const float* source = (const float*)d_in[0];
    const float* target = (const float*)d_in[1];
    const void*  eidx   = d_in[2];
    const int base = (n_in > 3 && in_sizes[3] == 1) ? 4 : 3;
    const float* W0 = (const float*)d_in[base + 0];
    const float* b0 = (const float*)d_in[base + 1];
    const float* W1 = (const float*)d_in[base + 2];
    const float* b1 = (const float*)d_in[base + 3];
    const float* W2 = (const float*)d_in[base + 4];
    const float* b2 = (const float*)d_in[base + 5];
    const float* W3 = (const float*)d_in[base + 6];
    const float* b3 = (const float*)d_in[base + 7];
    const float* gm = (const float*)d_in[base + 8];
    const float* bt = (const float*)d_in[base + 9];

    const int M = in_sizes[0] / HDIM;
    const int E = in_sizes[2] / 2;

    float *buf0, *buf1, *accum, *c2, *counts;
    cudaGetSymbolAddress((void**)&buf0,   g_buf0);
    cudaGetSymbolAddress((void**)&buf1,   g_buf1);
    cudaGetSymbolAddress((void**)&accum,  g_accum);
    cudaGetSymbolAddress((void**)&c2,     g_c2);
    cudaGetSymbolAddress((void**)&counts, g_counts);
    __nv_bfloat16 *w0h, *w0l, *w1h, *w1l, *w2h, *w2l, *w3h, *w3l;
    cudaGetSymbolAddress((void**)&w0h, g_w0h); cudaGetSymbolAddress((void**)&w0l, g_w0l);
    cudaGetSymbolAddress((void**)&w1h, g_w1h); cudaGetSymbolAddress((void**)&w1l, g_w1l);
    cudaGetSymbolAddress((void**)&w2h, g_w2h); cudaGetSymbolAddress((void**)&w2l, g_w2l);
    cudaGetSymbolAddress((void**)&w3h, g_w3h); cudaGetSymbolAddress((void**)&w3l, g_w3l);

    cudaFuncSetAttribute(gemm_mma<8, 0, 0>,  cudaFuncAttributeMaxDynamicSharedMemorySize, SM_TOTAL);
    cudaFuncSetAttribute(gemm_mma<16, 1, 0>, cudaFuncAttributeMaxDynamicSharedMemorySize, SM_TOTAL);
    cudaFuncSetAttribute(gemm_mma<8, 0, 1>,  cudaFuncAttributeMaxDynamicSharedMemorySize, SM_TOTAL);

    cudaMemsetAsync(accum, 0, sizeof(float) * (size_t)M * HDIM);
    cudaMemsetAsync(counts, 0, sizeof(float) * (size_t)M);

    detect_idx_kernel<<<1, 1>>>(eidx, M);
    wprep_kernel<<<(256 * 256 + 255) / 256, 256>>>(W0, w0h, w0l, 256, 256);
    wprep_kernel<<<(256 * 256 + 255) / 256, 256>>>(W1, w1h, w1l, 256, 256);
    wprep_kernel<<<(512 * 256 + 255) / 256, 256>>>(W2, w2h, w2l, 512, 256);
    wprep_kernel<<<(256 * 256 + 255) / 256, 256>>>(W3, w3h, w3l, 256, 256);

    const dim3 gG(2, (M + 127) / 128);
    gemm_mma<8, 0, 0><<<gG, 512, SM_TOTAL>>>(source, nullptr, nullptr, w0h, w0l, 256, b0, nullptr, buf0, M);
    gemm_mma<8, 0, 0><<<gG, 512, SM_TOTAL>>>(buf0,   nullptr, nullptr, w1h, w1l, 256, b1, nullptr, buf1, M);

    scatter_kernel<<<2960, 256>>>(eidx, buf1, accum, counts, E, M);

    gemm_mma<16, 1, 0><<<gG, 512, SM_TOTAL>>>(target, accum, counts, w2h, w2l, 512, b2, nullptr, c2, M);
    gemm_mma<8, 0, 1><<<gG, 512, SM_TOTAL>>>(c2, nullptr, nullptr, w3h, w3l, 256, b3, target, buf0, M);

    ln_kernel<<<(M * 32 + 255) / 256, 256>>>(buf0, gm, bt, (float*)d_out, M);
}

// round 7
// speedup vs baseline: 1.6569x; 1.0170x over previous
#include <cuda_runtime.h>
#include <cuda_bf16.h>
#include <cstdint>

#define HDIM 256
#define NMAX 50048

// ---------------- static scratch ----------------
__device__ float g_buf0[NMAX * HDIM];
__device__ float g_buf1[NMAX * HDIM];
__device__ float g_accum[NMAX * HDIM];
__device__ float g_c2[NMAX * HDIM];
__device__ float g_counts[NMAX];
__device__ int   g_idx64;

// split weights, transposed to [N, K] (K contiguous)
__device__ __nv_bfloat16 g_w0h[256 * 256], g_w0l[256 * 256];
__device__ __nv_bfloat16 g_w1h[256 * 256], g_w1l[256 * 256];
__device__ __nv_bfloat16 g_w2h[256 * 512], g_w2l[256 * 512];
__device__ __nv_bfloat16 g_w3h[256 * 256], g_w3l[256 * 256];

__device__ __forceinline__ float gelu_exact(float x) { return x * normcdff(x); }

__device__ __forceinline__ uint32_t smem_u32(const void* p) {
    uint32_t a;
    asm("{ .reg .u64 t; cvta.to.shared.u64 t, %1; cvt.u32.u64 %0, t; }" : "=r"(a) : "l"(p));
    return a;
}

#define LDMX4(r0, r1, r2, r3, a) \
    asm volatile("ldmatrix.sync.aligned.m8n8.x4.shared.b16 {%0,%1,%2,%3}, [%4];" \
        : "=r"(r0), "=r"(r1), "=r"(r2), "=r"(r3) : "r"(a))

#define MMA16816(c, a0, a1, a2, a3, b0, b1) \
    asm volatile("mma.sync.aligned.m16n8k16.row.col.f32.bf16.bf16.f32 " \
        "{%0,%1,%2,%3}, {%4,%5,%6,%7}, {%8,%9}, {%0,%1,%2,%3};" \
        : "+f"((c)[0]), "+f"((c)[1]), "+f"((c)[2]), "+f"((c)[3]) \
        : "r"(a0), "r"(a1), "r"(a2), "r"(a3), "r"(b0), "r"(b1))

#define CPASYNC16(sm, gp) \
    asm volatile("cp.async.cg.shared.global [%0], [%1], 16;" :: "r"(sm), "l"(gp))
#define CPASYNC_COMMIT() asm volatile("cp.async.commit_group;" ::: "memory")
#define CPASYNC_WAIT2()  asm volatile("cp.async.wait_group 2;" ::: "memory")

__device__ __forceinline__ uint32_t pack_bf2(__nv_bfloat16 a, __nv_bfloat16 b) {
    __nv_bfloat162 t = __halves2bfloat162(a, b);
    return *(uint32_t*)&t;
}

// ---------------- small kernels ----------------
__global__ void detect_idx_kernel(const void* eidx, int nnodes) {
    const long long* p = (const long long*)eidx;
    int ok64 = 1;
    #pragma unroll 1
    for (int i = 0; i < 64; i++) {
        long long v = p[i];
        if (v < 0 || v >= (long long)nnodes) { ok64 = 0; break; }
    }
    g_idx64 = ok64;
}

// All four W[K,N] fp32 -> Wt_hi/Wt_lo[N,K] bf16 splits in one launch.
__global__ void wprep_all_kernel(const float* __restrict__ W0,
                                 const float* __restrict__ W1,
                                 const float* __restrict__ W2,
                                 const float* __restrict__ W3) {
    int idx = blockIdx.x * blockDim.x + threadIdx.x;
    const float* W; __nv_bfloat16 *Wh, *Wl; int K;
    if (idx < 65536)       { W = W0; Wh = g_w0h; Wl = g_w0l; K = 256; }
    else if (idx < 131072) { W = W1; Wh = g_w1h; Wl = g_w1l; K = 256; idx -= 65536; }
    else if (idx < 262144) { W = W2; Wh = g_w2h; Wl = g_w2l; K = 512; idx -= 131072; }
    else if (idx < 327680) { W = W3; Wh = g_w3h; Wl = g_w3l; K = 256; idx -= 262144; }
    else return;
    const int n = idx / K, k = idx - n * K;
    const float w = W[(size_t)k * 256 + n];
    const __nv_bfloat16 h = __float2bfloat16_rn(w);
    Wh[idx] = h;
    Wl[idx] = __float2bfloat16_rn(w - __bfloat162float(h));
}

// ---------------- mma.sync GEMM (+bias+GELU [+residual]) ----------------
// C[M,256] = act(A @ Wt^T + b). 3xBF16 split. CTA 128x128, BK=32, 512 thr =
// 16 warps (4m x 4n), warp tile 32x32. A double-buffered (reg-staged convert),
// B 4-stage cp.async ring, one __syncthreads per chunk, wait_group 2.
// SMEM: A stages [0,20480),[20480,40960) (hi +0, lo +10240)
//       B stages 40960 + st*20480 (hi +0, lo +10240), st = ch & 3. Total 122880.
#define SA_BASE 0
#define SA_STAGE 20480
#define SB_BASE 40960
#define SB_STAGE 20480
#define HL_OFF 10240
#define SM_TOTAL 122880

template<int KCHUNKS, int SPLIT, int RESID>
__global__ __launch_bounds__(512, 1)
void gemm_mma(const float* __restrict__ A, const float* __restrict__ A2,
              const float* __restrict__ counts,
              const __nv_bfloat16* __restrict__ Wh, const __nv_bfloat16* __restrict__ Wl,
              int Kw, const float* __restrict__ bias, const float* __restrict__ resid,
              float* __restrict__ C, int M)
{
    extern __shared__ char smem[];
    const uint32_t sb = smem_u32(smem);
    const int tid = threadIdx.x;
    const int wid = tid >> 5, lane = tid & 31;
    const int rowBlock = blockIdx.y * 128;
    const int colBlock = blockIdx.x * 128;

    const int warp_m = wid & 3;
    const int warp_n = wid >> 2;

    float acc[2][4][4];
    #pragma unroll
    for (int a = 0; a < 2; a++)
        #pragma unroll
        for (int b = 0; b < 4; b++)
            #pragma unroll
            for (int c = 0; c < 4; c++) acc[a][b][c] = 0.0f;

    const int arow = tid >> 2;
    const int acb  = (tid & 3) * 8;

    const int a_rowin = (lane & 7) | (((lane >> 3) & 1) << 3);
    const int a_koff  = ((lane >> 4) & 1) * 8;
    const uint32_t a_byte = (uint32_t)((warp_m * 32 + a_rowin) * 80 + a_koff * 2);
    const int b_rowin = ((lane >> 4) & 1) * 8 + (lane & 7);
    const int b_koff  = ((lane >> 3) & 1) * 8;
    const uint32_t b_byte = (uint32_t)((warp_n * 32 + b_rowin) * 80 + b_koff * 2);

    float ar[8];
    auto loadA = [&](int ch) {
        const int gr = rowBlock + arow;
        #pragma unroll
        for (int j = 0; j < 8; j++) ar[j] = 0.0f;
        if (gr < M) {
            const int gk = ch * 32 + acb;
            const float* src;
            float sc = 1.0f;
            if (SPLIT && gk >= 256) {
                src = A2 + (size_t)gr * 256 + (gk - 256);
                sc = 1.0f / fmaxf(counts[gr], 1.0f);
            } else {
                src = A + (size_t)gr * 256 + gk;
            }
            float4 v0 = *(const float4*)src;
            float4 v1 = *(const float4*)(src + 4);
            ar[0] = v0.x * sc; ar[1] = v0.y * sc; ar[2] = v0.z * sc; ar[3] = v0.w * sc;
            ar[4] = v1.x * sc; ar[5] = v1.y * sc; ar[6] = v1.z * sc; ar[7] = v1.w * sc;
        }
    };
    auto storeA = [&](int stA) {
        uint32_t hp[4], lp[4];
        #pragma unroll
        for (int j = 0; j < 4; j++) {
            __nv_bfloat16 h0 = __float2bfloat16_rn(ar[2 * j]);
            __nv_bfloat16 h1 = __float2bfloat16_rn(ar[2 * j + 1]);
            __nv_bfloat16 l0 = __float2bfloat16_rn(ar[2 * j]     - __bfloat162float(h0));
            __nv_bfloat16 l1 = __float2bfloat16_rn(ar[2 * j + 1] - __bfloat162float(h1));
            hp[j] = pack_bf2(h0, h1);
            lp[j] = pack_bf2(l0, l1);
        }
        const uint32_t off = (uint32_t)(SA_BASE + stA * SA_STAGE + arow * 80 + acb * 2);
        *(uint4*)(smem + off)          = *(uint4*)&hp[0];
        *(uint4*)(smem + off + HL_OFF) = *(uint4*)&lp[0];
    };
    auto issueB = [&](int ch) {
        if (ch < KCHUNKS) {
            const int st = ch & 3;
            const uint32_t bh = sb + SB_BASE + st * SB_STAGE;
            const int n = tid >> 2, p = tid & 3;
            const size_t gofs = (size_t)(colBlock + n) * Kw + ch * 32 + p * 8;
            const uint32_t so = (uint32_t)(n * 80 + p * 16);
            CPASYNC16(bh + so, Wh + gofs);
            CPASYNC16(bh + HL_OFF + so, Wl + gofs);
        }
        CPASYNC_COMMIT();
    };

    issueB(0);
    issueB(1);
    loadA(0);
    storeA(0);

    for (int ch = 0; ch < KCHUNKS; ch++) {
        issueB(ch + 2);
        const bool more = (ch + 1 < KCHUNKS);
        if (more) loadA(ch + 1);
        CPASYNC_WAIT2();
        __syncthreads();

        const uint32_t aBase = sb + SA_BASE + (ch & 1) * SA_STAGE + a_byte;
        const uint32_t bBase = sb + SB_BASE + (ch & 3) * SB_STAGE + b_byte;
        #pragma unroll
        for (int s = 0; s < 2; s++) {
            uint32_t ah[2][4], al[2][4], bh[2][4], bl[2][4];
            #pragma unroll
            for (int mt = 0; mt < 2; mt++) {
                LDMX4(ah[mt][0], ah[mt][1], ah[mt][2], ah[mt][3], aBase + mt * 16 * 80 + s * 32);
                LDMX4(al[mt][0], al[mt][1], al[mt][2], al[mt][3], aBase + HL_OFF + mt * 16 * 80 + s * 32);
            }
            #pragma unroll
            for (int np = 0; np < 2; np++) {
                LDMX4(bh[np][0], bh[np][1], bh[np][2], bh[np][3], bBase + np * 16 * 80 + s * 32);
                LDMX4(bl[np][0], bl[np][1], bl[np][2], bl[np][3], bBase + HL_OFF + np * 16 * 80 + s * 32);
            }
            #pragma unroll
            for (int mt = 0; mt < 2; mt++)
                #pragma unroll
                for (int nt = 0; nt < 4; nt++) {
                    const int np = nt >> 1, ix = (nt & 1) * 2;
                    MMA16816(acc[mt][nt], ah[mt][0], ah[mt][1], ah[mt][2], ah[mt][3],
                             bh[np][ix], bh[np][ix + 1]);
                    MMA16816(acc[mt][nt], ah[mt][0], ah[mt][1], ah[mt][2], ah[mt][3],
                             bl[np][ix], bl[np][ix + 1]);
                    MMA16816(acc[mt][nt], al[mt][0], al[mt][1], al[mt][2], al[mt][3],
                             bh[np][ix], bh[np][ix + 1]);
                }
        }
        if (more) storeA((ch + 1) & 1);
    }

    // ---- epilogue ----
    const int qr = lane >> 2;
    const int qc = (lane & 3) * 2;
    float bv[4][2];
    #pragma unroll
    for (int nt = 0; nt < 4; nt++) {
        const int col = colBlock + warp_n * 32 + nt * 8 + qc;
        bv[nt][0] = bias[col];
        bv[nt][1] = bias[col + 1];
    }
    #pragma unroll
    for (int mt = 0; mt < 2; mt++)
        #pragma unroll
        for (int half = 0; half < 2; half++) {
            const int row = rowBlock + warp_m * 32 + mt * 16 + qr + half * 8;
            if (row >= M) continue;
            #pragma unroll
            for (int nt = 0; nt < 4; nt++) {
                const int col = colBlock + warp_n * 32 + nt * 8 + qc;
                float v0 = gelu_exact(acc[mt][nt][half * 2 + 0] + bv[nt][0]);
                float v1 = gelu_exact(acc[mt][nt][half * 2 + 1] + bv[nt][1]);
                if (RESID) {
                    const float2 rv = *(const float2*)(resid + (size_t)row * 256 + col);
                    v0 += rv.x; v1 += rv.y;
                }
                float2 o = make_float2(v0, v1);
                *(float2*)(C + (size_t)row * 256 + col) = o;
            }
        }
}

// ---------------- edge scatter-sum ----------------
__global__ void scatter_kernel(const void* __restrict__ eidx,
                               const float* __restrict__ msg,
                               float* __restrict__ accum,
                               float* __restrict__ counts,
                               int E, int Nn)
{
    const int lane = threadIdx.x & 31;
    const int warp = (blockIdx.x * blockDim.x + threadIdx.x) >> 5;
    const int nwarps = (gridDim.x * blockDim.x) >> 5;
    const int flag = g_idx64;
    const long long* p64 = (const long long*)eidx;
    const int*       p32 = (const int*)eidx;

    for (int e = warp; e < E; e += nwarps) {
        int src, dst;
        if (flag) { src = (int)p64[e]; dst = (int)p64[E + e]; }
        else      { src = p32[e];      dst = p32[E + e]; }
        src = min(max(src, 0), Nn - 1);
        dst = min(max(dst, 0), Nn - 1);

        const float4* srow = (const float4*)(msg + (size_t)src * 256);
        const float4 v0 = srow[lane * 2 + 0];
        const float4 v1 = srow[lane * 2 + 1];
        float* d = accum + (size_t)dst * 256 + lane * 8;
        asm volatile("red.global.add.v4.f32 [%0], {%1,%2,%3,%4};"
                     :: "l"(d), "f"(v0.x), "f"(v0.y), "f"(v0.z), "f"(v0.w) : "memory");
        asm volatile("red.global.add.v4.f32 [%0], {%1,%2,%3,%4};"
                     :: "l"(d + 4), "f"(v1.x), "f"(v1.y), "f"(v1.z), "f"(v1.w) : "memory");
        if (lane == 0)
            asm volatile("red.global.add.f32 [%0], %1;"
                         :: "l"(counts + dst), "f"(1.0f) : "memory");
    }
}

// ---------------- LayerNorm (warp per row) ----------------
__global__ __launch_bounds__(256)
void ln_kernel(const float* __restrict__ X, const float* __restrict__ gamma,
               const float* __restrict__ beta, float* __restrict__ out, int M)
{
    const int warp = (blockIdx.x * blockDim.x + threadIdx.x) >> 5;
    const int lane = threadIdx.x & 31;
    if (warp >= M) return;
    const float* xp = X + (size_t)warp * 256 + lane * 8;
    float v[8];
    *(float4*)&v[0] = *(const float4*)(xp);
    *(float4*)&v[4] = *(const float4*)(xp + 4);
    float s = 0.f, sq = 0.f;
    #pragma unroll
    for (int j = 0; j < 8; j++) { s += v[j]; sq += v[j] * v[j]; }
    #pragma unroll
    for (int off = 16; off > 0; off >>= 1) {
        s  += __shfl_xor_sync(0xFFFFFFFFu, s,  off);
        sq += __shfl_xor_sync(0xFFFFFFFFu, sq, off);
    }
    const float mu  = s * (1.0f / 256.0f);
    const float var = sq * (1.0f / 256.0f) - mu * mu;
    const float inv = rsqrtf(var + 1e-5f);
    float o[8];
    #pragma unroll
    for (int j = 0; j < 8; j++)
        o[j] = (v[j] - mu) * inv * gamma[lane * 8 + j] + beta[lane * 8 + j];
    float* dp = out + (size_t)warp * 256 + lane * 8;
    *(float4*)(dp)     = *(float4*)&o[0];
    *(float4*)(dp + 4) = *(float4*)&o[4];
}

// ---------------- launch ----------------
extern "C" void kernel_launch(void* const* d_in, const int* in_sizes, int n_in,
                              void* d_out, int out_size)
{
    const float* source = (const float*)d_in[0];
    const float* target = (const float*)d_in[1];
    const void*  eidx   = d_in[2];
    const int base = (n_in > 3 && in_sizes[3] == 1) ? 4 : 3;
    const float* W0 = (const float*)d_in[base + 0];
    const float* b0 = (const float*)d_in[base + 1];
    const float* W1 = (const float*)d_in[base + 2];
    const float* b1 = (const float*)d_in[base + 3];
    const float* W2 = (const float*)d_in[base + 4];
    const float* b2 = (const float*)d_in[base + 5];
    const float* W3 = (const float*)d_in[base + 6];
    const float* b3 = (const float*)d_in[base + 7];
    const float* gm = (const float*)d_in[base + 8];
    const float* bt = (const float*)d_in[base + 9];

    const int M = in_sizes[0] / HDIM;
    const int E = in_sizes[2] / 2;

    float *buf0, *buf1, *accum, *c2, *counts;
    cudaGetSymbolAddress((void**)&buf0,   g_buf0);
    cudaGetSymbolAddress((void**)&buf1,   g_buf1);
    cudaGetSymbolAddress((void**)&accum,  g_accum);
    cudaGetSymbolAddress((void**)&c2,     g_c2);
    cudaGetSymbolAddress((void**)&counts, g_counts);
    __nv_bfloat16 *w0h, *w0l, *w1h, *w1l, *w2h, *w2l, *w3h, *w3l;
    cudaGetSymbolAddress((void**)&w0h, g_w0h); cudaGetSymbolAddress((void**)&w0l, g_w0l);
    cudaGetSymbolAddress((void**)&w1h, g_w1h); cudaGetSymbolAddress((void**)&w1l, g_w1l);
    cudaGetSymbolAddress((void**)&w2h, g_w2h); cudaGetSymbolAddress((void**)&w2l, g_w2l);
    cudaGetSymbolAddress((void**)&w3h, g_w3h); cudaGetSymbolAddress((void**)&w3l, g_w3l);

    cudaFuncSetAttribute(gemm_mma<8, 0, 0>,  cudaFuncAttributeMaxDynamicSharedMemorySize, SM_TOTAL);
    cudaFuncSetAttribute(gemm_mma<16, 1, 0>, cudaFuncAttributeMaxDynamicSharedMemorySize, SM_TOTAL);
    cudaFuncSetAttribute(gemm_mma<8, 0, 1>,  cudaFuncAttributeMaxDynamicSharedMemorySize, SM_TOTAL);

    // Launch order tuned so ncu's "-s 5 -c 1" capture slot lands on gemm2:
    //  0 memset, 1 memset, 2 wprep_all, 3 detect, 4 gemm1, 5 gemm2 <- captured
    cudaMemsetAsync(accum, 0, sizeof(float) * (size_t)M * HDIM);
    cudaMemsetAsync(counts, 0, sizeof(float) * (size_t)M);
    wprep_all_kernel<<<(327680 + 255) / 256, 256>>>(W0, W1, W2, W3);
    detect_idx_kernel<<<1, 1>>>(eidx, M);

    const dim3 gG(2, (M + 127) / 128);
    gemm_mma<8, 0, 0><<<gG, 512, SM_TOTAL>>>(source, nullptr, nullptr, w0h, w0l, 256, b0, nullptr, buf0, M);
    gemm_mma<8, 0, 0><<<gG, 512, SM_TOTAL>>>(buf0,   nullptr, nullptr, w1h, w1l, 256, b1, nullptr, buf1, M);

    scatter_kernel<<<2960, 256>>>(eidx, buf1, accum, counts, E, M);

    gemm_mma<16, 1, 0><<<gG, 512, SM_TOTAL>>>(target, accum, counts, w2h, w2l, 512, b2, nullptr, c2, M);
    gemm_mma<8, 0, 1><<<gG, 512, SM_TOTAL>>>(c2, nullptr, nullptr, w3h, w3l, 256, b3, target, buf0, M);

    ln_kernel<<<(M * 32 + 255) / 256, 256>>>(buf0, gm, bt, (float*)d_out, M);
}

// round 10
// speedup vs baseline: 1.7450x; 1.0532x over previous
#include <cuda_runtime.h>
#include <cuda_bf16.h>
#include <cstdint>

#define HDIM 256
#define NMAX 50048

// ---------------- static scratch ----------------
__device__ float g_buf0[NMAX * HDIM];
__device__ float g_buf1[NMAX * HDIM];
__device__ float g_accum[NMAX * HDIM];
__device__ float g_c2[NMAX * HDIM];
__device__ float g_counts[NMAX];
__device__ int   g_idx64;

// split weights, transposed to [N, K] (K contiguous)
__device__ __nv_bfloat16 g_w0h[256 * 256], g_w0l[256 * 256];
__device__ __nv_bfloat16 g_w1h[256 * 256], g_w1l[256 * 256];
__device__ __nv_bfloat16 g_w2h[256 * 512], g_w2l[256 * 512];
__device__ __nv_bfloat16 g_w3h[256 * 256], g_w3l[256 * 256];

__device__ __forceinline__ float gelu_exact(float x) { return x * normcdff(x); }

__device__ __forceinline__ uint32_t smem_u32(const void* p) {
    uint32_t a;
    asm("{ .reg .u64 t; cvta.to.shared.u64 t, %1; cvt.u32.u64 %0, t; }" : "=r"(a) : "l"(p));
    return a;
}

#define LDMX4(r0, r1, r2, r3, a) \
    asm volatile("ldmatrix.sync.aligned.m8n8.x4.shared.b16 {%0,%1,%2,%3}, [%4];" \
        : "=r"(r0), "=r"(r1), "=r"(r2), "=r"(r3) : "r"(a))

#define MMA16816(c, a0, a1, a2, a3, b0, b1) \
    asm volatile("mma.sync.aligned.m16n8k16.row.col.f32.bf16.bf16.f32 " \
        "{%0,%1,%2,%3}, {%4,%5,%6,%7}, {%8,%9}, {%0,%1,%2,%3};" \
        : "+f"((c)[0]), "+f"((c)[1]), "+f"((c)[2]), "+f"((c)[3]) \
        : "r"(a0), "r"(a1), "r"(a2), "r"(a3), "r"(b0), "r"(b1))

#define CPASYNC16(sm, gp) \
    asm volatile("cp.async.cg.shared.global [%0], [%1], 16;" :: "r"(sm), "l"(gp))
#define CPASYNC_COMMIT() asm volatile("cp.async.commit_group;" ::: "memory")
#define CPASYNC_WAIT2()  asm volatile("cp.async.wait_group 2;" ::: "memory")

__device__ __forceinline__ uint32_t pack_bf2(__nv_bfloat16 a, __nv_bfloat16 b) {
    __nv_bfloat162 t = __halves2bfloat162(a, b);
    return *(uint32_t*)&t;
}

// ---------------- small kernels ----------------
__global__ void detect_idx_kernel(const void* eidx, int nnodes) {
    const long long* p = (const long long*)eidx;
    int ok64 = 1;
    #pragma unroll 1
    for (int i = 0; i < 64; i++) {
        long long v = p[i];
        if (v < 0 || v >= (long long)nnodes) { ok64 = 0; break; }
    }
    g_idx64 = ok64;
}

// All four W[K,N] fp32 -> Wt_hi/Wt_lo[N,K] bf16 splits in one launch.
__global__ void wprep_all_kernel(const float* __restrict__ W0,
                                 const float* __restrict__ W1,
                                 const float* __restrict__ W2,
                                 const float* __restrict__ W3) {
    int idx = blockIdx.x * blockDim.x + threadIdx.x;
    const float* W; __nv_bfloat16 *Wh, *Wl; int K;
    if (idx < 65536)       { W = W0; Wh = g_w0h; Wl = g_w0l; K = 256; }
    else if (idx < 131072) { W = W1; Wh = g_w1h; Wl = g_w1l; K = 256; idx -= 65536; }
    else if (idx < 262144) { W = W2; Wh = g_w2h; Wl = g_w2l; K = 512; idx -= 131072; }
    else if (idx < 327680) { W = W3; Wh = g_w3h; Wl = g_w3l; K = 256; idx -= 262144; }
    else return;
    const int n = idx / K, k = idx - n * K;
    const float w = W[(size_t)k * 256 + n];
    const __nv_bfloat16 h = __float2bfloat16_rn(w);
    Wh[idx] = h;
    Wl[idx] = __float2bfloat16_rn(w - __bfloat162float(h));
}

// ---------------- mma.sync GEMM (+bias+GELU [+residual]) ----------------
// C[M,256] = act(A @ Wt^T + b). 3xBF16 split. CTA tile 64x128, BK=32, 256 thr
// = 8 warps (2m x 4n), warp tile 32x32. Sized for 2 CTAs per SM (independent
// barrier domains overlap each other's sync stalls).
// SMEM: A stages [0,10240),[10240,20480)  (hi +0, lo +5120)
//       B stages 20480 + st*20480 (hi +0, lo +10240), st = ch & 3.
// Total 102400 -> 2 CTAs fit; regs capped by launch_bounds(256,2).
#define SA_BASE 0
#define SA_STAGE 10240
#define HLA_OFF 5120
#define SB_BASE 20480
#define SB_STAGE 20480
#define HLB_OFF 10240
#define SM_TOTAL 102400

template<int KCHUNKS, int SPLIT, int RESID>
__global__ __launch_bounds__(256, 2)
void gemm_mma(const float* __restrict__ A, const float* __restrict__ A2,
              const float* __restrict__ counts,
              const __nv_bfloat16* __restrict__ Wh, const __nv_bfloat16* __restrict__ Wl,
              int Kw, const float* __restrict__ bias, const float* __restrict__ resid,
              float* __restrict__ C, int M)
{
    extern __shared__ char smem[];
    const uint32_t sb = smem_u32(smem);
    const int tid = threadIdx.x;
    const int wid = tid >> 5, lane = tid & 31;
    const int rowBlock = blockIdx.y * 64;
    const int colBlock = blockIdx.x * 128;

    const int warp_m = wid & 1;          // 0..1 -> m offset *32
    const int warp_n = wid >> 1;         // 0..3 -> n offset *32

    float acc[2][4][4];
    #pragma unroll
    for (int a = 0; a < 2; a++)
        #pragma unroll
        for (int b = 0; b < 4; b++)
            #pragma unroll
            for (int c = 0; c < 4; c++) acc[a][b][c] = 0.0f;

    // A staging: thread -> row tid/4 (0..63), 8 cols at (tid&3)*8
    const int arow = tid >> 2;
    const int acb  = (tid & 3) * 8;

    // ldmatrix per-lane addressing (stride 80 bytes per row)
    const int a_rowin = (lane & 7) | (((lane >> 3) & 1) << 3);
    const int a_koff  = ((lane >> 4) & 1) * 8;
    const uint32_t a_byte = (uint32_t)((warp_m * 32 + a_rowin) * 80 + a_koff * 2);
    const int b_rowin = ((lane >> 4) & 1) * 8 + (lane & 7);
    const int b_koff  = ((lane >> 3) & 1) * 8;
    const uint32_t b_byte = (uint32_t)((warp_n * 32 + b_rowin) * 80 + b_koff * 2);

    float ar[8];
    auto loadA = [&](int ch) {
        const int gr = rowBlock + arow;
        #pragma unroll
        for (int j = 0; j < 8; j++) ar[j] = 0.0f;
        if (gr < M) {
            const int gk = ch * 32 + acb;
            const float* src;
            float sc = 1.0f;
            if (SPLIT && gk >= 256) {
                src = A2 + (size_t)gr * 256 + (gk - 256);
                sc = 1.0f / fmaxf(counts[gr], 1.0f);
            } else {
                src = A + (size_t)gr * 256 + gk;
            }
            float4 v0 = *(const float4*)src;
            float4 v1 = *(const float4*)(src + 4);
            ar[0] = v0.x * sc; ar[1] = v0.y * sc; ar[2] = v0.z * sc; ar[3] = v0.w * sc;
            ar[4] = v1.x * sc; ar[5] = v1.y * sc; ar[6] = v1.z * sc; ar[7] = v1.w * sc;
        }
    };
    auto storeA = [&](int stA) {
        uint32_t hp[4], lp[4];
        #pragma unroll
        for (int j = 0; j < 4; j++) {
            __nv_bfloat16 h0 = __float2bfloat16_rn(ar[2 * j]);
            __nv_bfloat16 h1 = __float2bfloat16_rn(ar[2 * j + 1]);
            __nv_bfloat16 l0 = __float2bfloat16_rn(ar[2 * j]     - __bfloat162float(h0));
            __nv_bfloat16 l1 = __float2bfloat16_rn(ar[2 * j + 1] - __bfloat162float(h1));
            hp[j] = pack_bf2(h0, h1);
            lp[j] = pack_bf2(l0, l1);
        }
        const uint32_t off = (uint32_t)(SA_BASE + stA * SA_STAGE + arow * 80 + acb * 2);
        *(uint4*)(smem + off)           = *(uint4*)&hp[0];
        *(uint4*)(smem + off + HLA_OFF) = *(uint4*)&lp[0];
    };
    auto issueB = [&](int ch) {
        if (ch < KCHUNKS) {
            const int st = ch & 3;
            const uint32_t bh = sb + SB_BASE + st * SB_STAGE;
            #pragma unroll
            for (int q = 0; q < 2; q++) {
                const int s = tid * 2 + q;       // 0..511
                const int n = s >> 2, p = s & 3;
                const size_t gofs = (size_t)(colBlock + n) * Kw + ch * 32 + p * 8;
                const uint32_t so = (uint32_t)(n * 80 + p * 16);
                CPASYNC16(bh + so, Wh + gofs);
                CPASYNC16(bh + HLB_OFF + so, Wl + gofs);
            }
        }
        CPASYNC_COMMIT();
    };

    issueB(0);
    issueB(1);
    loadA(0);
    storeA(0);

    #pragma unroll 1
    for (int ch = 0; ch < KCHUNKS; ch++) {
        issueB(ch + 2);
        const bool more = (ch + 1 < KCHUNKS);
        if (more) loadA(ch + 1);
        CPASYNC_WAIT2();
        __syncthreads();

        const uint32_t aBase = sb + SA_BASE + (ch & 1) * SA_STAGE + a_byte;
        const uint32_t bBase = sb + SB_BASE + (ch & 3) * SB_STAGE + b_byte;
        #pragma unroll
        for (int s = 0; s < 2; s++) {
            uint32_t ah[4], al[4], bh[2][4], bl[2][4];
            LDMX4(ah[0], ah[1], ah[2], ah[3], aBase + s * 32);
            LDMX4(al[0], al[1], al[2], al[3], aBase + HLA_OFF + s * 32);
            #pragma unroll
            for (int np = 0; np < 2; np++) {
                LDMX4(bh[np][0], bh[np][1], bh[np][2], bh[np][3], bBase + np * 16 * 80 + s * 32);
                LDMX4(bl[np][0], bl[np][1], bl[np][2], bl[np][3], bBase + HLB_OFF + np * 16 * 80 + s * 32);
            }
            uint32_t ah2[4], al2[4];
            LDMX4(ah2[0], ah2[1], ah2[2], ah2[3], aBase + 16 * 80 + s * 32);
            LDMX4(al2[0], al2[1], al2[2], al2[3], aBase + HLA_OFF + 16 * 80 + s * 32);
            #pragma unroll
            for (int nt = 0; nt < 4; nt++) {
                const int np = nt >> 1, ix = (nt & 1) * 2;
                MMA16816(acc[0][nt], ah[0], ah[1], ah[2], ah[3], bh[np][ix], bh[np][ix + 1]);
                MMA16816(acc[0][nt], ah[0], ah[1], ah[2], ah[3], bl[np][ix], bl[np][ix + 1]);
                MMA16816(acc[0][nt], al[0], al[1], al[2], al[3], bh[np][ix], bh[np][ix + 1]);
                MMA16816(acc[1][nt], ah2[0], ah2[1], ah2[2], ah2[3], bh[np][ix], bh[np][ix + 1]);
                MMA16816(acc[1][nt], ah2[0], ah2[1], ah2[2], ah2[3], bl[np][ix], bl[np][ix + 1]);
                MMA16816(acc[1][nt], al2[0], al2[1], al2[2], al2[3], bh[np][ix], bh[np][ix + 1]);
            }
        }
        if (more) storeA((ch + 1) & 1);
    }

    // ---- epilogue ----
    const int qr = lane >> 2;
    const int qc = (lane & 3) * 2;
    float bv[4][2];
    #pragma unroll
    for (int nt = 0; nt < 4; nt++) {
        const int col = colBlock + warp_n * 32 + nt * 8 + qc;
        bv[nt][0] = bias[col];
        bv[nt][1] = bias[col + 1];
    }
    #pragma unroll
    for (int mt = 0; mt < 2; mt++)
        #pragma unroll
        for (int half = 0; half < 2; half++) {
            const int row = rowBlock + warp_m * 32 + mt * 16 + qr + half * 8;
            if (row >= M) continue;
            #pragma unroll
            for (int nt = 0; nt < 4; nt++) {
                const int col = colBlock + warp_n * 32 + nt * 8 + qc;
                float v0 = gelu_exact(acc[mt][nt][half * 2 + 0] + bv[nt][0]);
                float v1 = gelu_exact(acc[mt][nt][half * 2 + 1] + bv[nt][1]);
                if (RESID) {
                    const float2 rv = *(const float2*)(resid + (size_t)row * 256 + col);
                    v0 += rv.x; v1 += rv.y;
                }
                float2 o = make_float2(v0, v1);
                *(float2*)(C + (size_t)row * 256 + col) = o;
            }
        }
}

// ---------------- edge scatter-sum (2 edges per warp iteration for MLP) ----------------
__global__ void scatter_kernel(const void* __restrict__ eidx,
                               const float* __restrict__ msg,
                               float* __restrict__ accum,
                               float* __restrict__ counts,
                               int E, int Nn)
{
    const int lane = threadIdx.x & 31;
    const int warp = (blockIdx.x * blockDim.x + threadIdx.x) >> 5;
    const int nwarps = (gridDim.x * blockDim.x) >> 5;
    const int flag = g_idx64;
    const long long* p64 = (const long long*)eidx;
    const int*       p32 = (const int*)eidx;

    #pragma unroll 1
    for (int e = warp * 2; e < E; e += nwarps * 2) {
        const int e1ok = (e + 1 < E);
        int src0, dst0, src1 = 0, dst1 = 0;
        if (flag) {
            src0 = (int)p64[e]; dst0 = (int)p64[E + e];
            if (e1ok) { src1 = (int)p64[e + 1]; dst1 = (int)p64[E + e + 1]; }
        } else {
            src0 = p32[e]; dst0 = p32[E + e];
            if (e1ok) { src1 = p32[e + 1]; dst1 = p32[E + e + 1]; }
        }
        src0 = min(max(src0, 0), Nn - 1); dst0 = min(max(dst0, 0), Nn - 1);
        src1 = min(max(src1, 0), Nn - 1); dst1 = min(max(dst1, 0), Nn - 1);

        const float4* s0 = (const float4*)(msg + (size_t)src0 * 256);
        const float4* s1 = (const float4*)(msg + (size_t)src1 * 256);
        const float4 a0 = s0[lane * 2 + 0];
        const float4 a1 = s0[lane * 2 + 1];
        float4 b0 = make_float4(0.f, 0.f, 0.f, 0.f);
        float4 b1 = make_float4(0.f, 0.f, 0.f, 0.f);
        if (e1ok) { b0 = s1[lane * 2 + 0]; b1 = s1[lane * 2 + 1]; }

        float* d0 = accum + (size_t)dst0 * 256 + lane * 8;
        asm volatile("red.global.add.v4.f32 [%0], {%1,%2,%3,%4};"
                     :: "l"(d0), "f"(a0.x), "f"(a0.y), "f"(a0.z), "f"(a0.w) : "memory");
        asm volatile("red.global.add.v4.f32 [%0], {%1,%2,%3,%4};"
                     :: "l"(d0 + 4), "f"(a1.x), "f"(a1.y), "f"(a1.z), "f"(a1.w) : "memory");
        if (e1ok) {
            float* d1 = accum + (size_t)dst1 * 256 + lane * 8;
            asm volatile("red.global.add.v4.f32 [%0], {%1,%2,%3,%4};"
                         :: "l"(d1), "f"(b0.x), "f"(b0.y), "f"(b0.z), "f"(b0.w) : "memory");
            asm volatile("red.global.add.v4.f32 [%0], {%1,%2,%3,%4};"
                         :: "l"(d1 + 4), "f"(b1.x), "f"(b1.y), "f"(b1.z), "f"(b1.w) : "memory");
        }
        if (lane == 0) {
            asm volatile("red.global.add.f32 [%0], %1;"
                         :: "l"(counts + dst0), "f"(1.0f) : "memory");
            if (e1ok)
                asm volatile("red.global.add.f32 [%0], %1;"
                             :: "l"(counts + dst1), "f"(1.0f) : "memory");
        }
    }
}

// ---------------- LayerNorm (warp per row) ----------------
__global__ __launch_bounds__(256)
void ln_kernel(const float* __restrict__ X, const float* __restrict__ gamma,
               const float* __restrict__ beta, float* __restrict__ out, int M)
{
    const int warp = (blockIdx.x * blockDim.x + threadIdx.x) >> 5;
    const int lane = threadIdx.x & 31;
    if (warp >= M) return;
    const float* xp = X + (size_t)warp * 256 + lane * 8;
    float v[8];
    *(float4*)&v[0] = *(const float4*)(xp);
    *(float4*)&v[4] = *(const float4*)(xp + 4);
    float s = 0.f, sq = 0.f;
    #pragma unroll
    for (int j = 0; j < 8; j++) { s += v[j]; sq += v[j] * v[j]; }
    #pragma unroll
    for (int off = 16; off > 0; off >>= 1) {
        s  += __shfl_xor_sync(0xFFFFFFFFu, s,  off);
        sq += __shfl_xor_sync(0xFFFFFFFFu, sq, off);
    }
    const float mu  = s * (1.0f / 256.0f);
    const float var = sq * (1.0f / 256.0f) - mu * mu;
    const float inv = rsqrtf(var + 1e-5f);
    float o[8];
    #pragma unroll
    for (int j = 0; j < 8; j++)
        o[j] = (v[j] - mu) * inv * gamma[lane * 8 + j] + beta[lane * 8 + j];
    float* dp = out + (size_t)warp * 256 + lane * 8;
    *(float4*)(dp)     = *(float4*)&o[0];
    *(float4*)(dp + 4) = *(float4*)&o[4];
}

// ---------------- launch ----------------
extern "C" void kernel_launch(void* const* d_in, const int* in_sizes, int n_in,
                              void* d_out, int out_size)
{
    const float* source = (const float*)d_in[0];
    const float* target = (const float*)d_in[1];
    const void*  eidx   = d_in[2];
    const int base = (n_in > 3 && in_sizes[3] == 1) ? 4 : 3;
    const float* W0 = (const float*)d_in[base + 0];
    const float* b0 = (const float*)d_in[base + 1];
    const float* W1 = (const float*)d_in[base + 2];
    const float* b1 = (const float*)d_in[base + 3];
    const float* W2 = (const float*)d_in[base + 4];
    const float* b2 = (const float*)d_in[base + 5];
    const float* W3 = (const float*)d_in[base + 6];
    const float* b3 = (const float*)d_in[base + 7];
    const float* gm = (const float*)d_in[base + 8];
    const float* bt = (const float*)d_in[base + 9];

    const int M = in_sizes[0] / HDIM;
    const int E = in_sizes[2] / 2;

    float *buf0, *buf1, *accum, *c2, *counts;
    cudaGetSymbolAddress((void**)&buf0,   g_buf0);
    cudaGetSymbolAddress((void**)&buf1,   g_buf1);
    cudaGetSymbolAddress((void**)&accum,  g_accum);
    cudaGetSymbolAddress((void**)&c2,     g_c2);
    cudaGetSymbolAddress((void**)&counts, g_counts);
    __nv_bfloat16 *w0h, *w0l, *w1h, *w1l, *w2h, *w2l, *w3h, *w3l;
    cudaGetSymbolAddress((void**)&w0h, g_w0h); cudaGetSymbolAddress((void**)&w0l, g_w0l);
    cudaGetSymbolAddress((void**)&w1h, g_w1h); cudaGetSymbolAddress((void**)&w1l, g_w1l);
    cudaGetSymbolAddress((void**)&w2h, g_w2h); cudaGetSymbolAddress((void**)&w2l, g_w2l);
    cudaGetSymbolAddress((void**)&w3h, g_w3h); cudaGetSymbolAddress((void**)&w3l, g_w3l);

    cudaFuncSetAttribute(gemm_mma<8, 0, 0>,  cudaFuncAttributeMaxDynamicSharedMemorySize, SM_TOTAL);
    cudaFuncSetAttribute(gemm_mma<16, 1, 0>, cudaFuncAttributeMaxDynamicSharedMemorySize, SM_TOTAL);
    cudaFuncSetAttribute(gemm_mma<8, 0, 1>,  cudaFuncAttributeMaxDynamicSharedMemorySize, SM_TOTAL);

    // Launch order keeps ncu "-s 5 -c 1" on gemm2:
    //  0 memset, 1 memset, 2 wprep_all, 3 detect, 4 gemm1, 5 gemm2 <- captured
    cudaMemsetAsync(accum, 0, sizeof(float) * (size_t)M * HDIM);
    cudaMemsetAsync(counts, 0, sizeof(float) * (size_t)M);
    wprep_all_kernel<<<(327680 + 255) / 256, 256>>>(W0, W1, W2, W3);
    detect_idx_kernel<<<1, 1>>>(eidx, M);

    const dim3 gG(2, (M + 63) / 64);
    gemm_mma<8, 0, 0><<<gG, 256, SM_TOTAL>>>(source, nullptr, nullptr, w0h, w0l, 256, b0, nullptr, buf0, M);
    gemm_mma<8, 0, 0><<<gG, 256, SM_TOTAL>>>(buf0,   nullptr, nullptr, w1h, w1l, 256, b1, nullptr, buf1, M);

    scatter_kernel<<<2960, 256>>>(eidx, buf1, accum, counts, E, M);

    gemm_mma<16, 1, 0><<<gG, 256, SM_TOTAL>>>(target, accum, counts, w2h, w2l, 512, b2, nullptr, c2, M);
    gemm_mma<8, 0, 1><<<gG, 256, SM_TOTAL>>>(c2, nullptr, nullptr, w3h, w3l, 256, b3, target, buf0, M);

    ln_kernel<<<(M * 32 + 255) / 256, 256>>>(buf0, gm, bt, (float*)d_out, M);
}